// round 16
// baseline (speedup 1.0000x reference)
#include <cuda_runtime.h>
#include <cuda_fp16.h>
#include <math.h>

#define BB 4
#define SS 2048
#define DD 1024
#define HH 16
#define HDIM 64
#define NT (BB*SS)   // 8192 tokens
#define P2 72        // smem pitch (fp16 elems) = 144B rows, ldsm conflict-free

// ---- fp16 scratch (static device globals — allocation-free) ----
__device__ __half g_xf[(size_t)NT*DD];
__device__ __half g_wf[4][(size_t)DD*DD];            // Wq,Wk,Wv,Wo
__device__ __half g_Qf[(size_t)BB*HH*SS*HDIM];
__device__ __half g_Kf[(size_t)BB*HH*SS*HDIM];
__device__ __half g_Vf[(size_t)BB*HH*SS*HDIM];
__device__ __half g_af[(size_t)NT*DD];               // att [t,d]

#define MMA_F16(d, a, b0, b1)                                              \
    asm("mma.sync.aligned.m16n8k16.row.col.f32.f16.f16.f32 "               \
        "{%0,%1,%2,%3}, {%4,%5,%6,%7}, {%8,%9}, {%0,%1,%2,%3};"            \
        : "+f"(d[0]), "+f"(d[1]), "+f"(d[2]), "+f"(d[3])                   \
        : "r"(a[0]), "r"(a[1]), "r"(a[2]), "r"(a[3]), "r"(b0), "r"(b1))

__device__ __forceinline__ void ldsm4(unsigned* r, unsigned a) {
    asm volatile("ldmatrix.sync.aligned.m8n8.x4.shared.b16 {%0,%1,%2,%3}, [%4];"
                 : "=r"(r[0]), "=r"(r[1]), "=r"(r[2]), "=r"(r[3]) : "r"(a));
}
__device__ __forceinline__ void ldsm4t(unsigned* r, unsigned a) {
    asm volatile("ldmatrix.sync.aligned.m8n8.x4.trans.shared.b16 {%0,%1,%2,%3}, [%4];"
                 : "=r"(r[0]), "=r"(r[1]), "=r"(r[2]), "=r"(r[3]) : "r"(a));
}
__device__ __forceinline__ unsigned smem_u32(const void* p) {
    return (unsigned)__cvta_generic_to_shared(p);
}
__device__ __forceinline__ unsigned packh(float a, float b) {
    __half2 t = __floats2half2_rn(a, b);
    return reinterpret_cast<unsigned&>(t);
}
__device__ __forceinline__ void cpa16(unsigned dst, const void* src) {
    asm volatile("cp.async.cg.shared.global [%0], [%1], 16;" :: "r"(dst), "l"(src));
}
#define CP_COMMIT() asm volatile("cp.async.commit_group;")
#define CP_WAIT(N)  asm volatile("cp.async.wait_group %0;" :: "n"(N))

// ---------------------------------------------------------------------------
// Kernel 0: fused fp32 -> fp16 of x + 4 weights.
// ---------------------------------------------------------------------------
__global__ __launch_bounds__(256) void cvt_all(
    const float* __restrict__ x,
    const float* __restrict__ Wq, const float* __restrict__ Wk,
    const float* __restrict__ Wv, const float* __restrict__ Wo)
{
    const size_t NX = (size_t)NT*DD;
    const size_t NW = (size_t)DD*DD;
    size_t i = ((size_t)blockIdx.x*256 + threadIdx.x) * 4;
    const float* src; __half* df; size_t off;
    if (i < NX) { src = x; df = g_xf; off = i; }
    else {
        size_t j = i - NX;
        int w = (int)(j / NW);
        off = j - (size_t)w*NW;
        src = (w==0)?Wq:(w==1)?Wk:(w==2)?Wv:Wo;
        df = g_wf[w];
    }
    float4 v = *(const float4*)&src[off];
    *(uint2*)&df[off] = make_uint2(packh(v.x, v.y), packh(v.z, v.w));
}

// ---------------------------------------------------------------------------
// fp16 GEMM mainloop: 128M x 128N tile, k-chunk 64, 3-stage cp.async ring,
// ONE barrier per chunk (issue placed after the sync: stage (kc+2)%3 ==
// (kc-1)%3 whose readers finished before this sync).
// ---------------------------------------------------------------------------
#define OFF_B7  (128*P2*2)            // 18432
#define STG7    (2*128*P2*2)          // 36864
#define GSM8    (3*STG7)              // 110592

__device__ __forceinline__ void run_gemm8(
    const __half* __restrict__ Af, const __half* __restrict__ Bf,
    int t0, int n0, unsigned sbase, float acc[2][8][4])
{
    const int tid  = threadIdx.x;
    const int lane = tid & 31;
    const int warp = tid >> 5;
    const int wm   = warp & 3;
    const int wn   = warp >> 2;
    const int g = lane >> 3, lr = lane & 7;

    const unsigned aoff0 = (unsigned)((wm*32 +      (g&1)*8 + lr)*P2 + (g>>1)*8) * 2;
    const unsigned aoff1 = (unsigned)((wm*32 + 16 + (g&1)*8 + lr)*P2 + (g>>1)*8) * 2;
    const unsigned boff  = (unsigned)((wn*64 + (g&1)*8 + lr)*P2 + (g>>1)*8) * 2;

    auto issue = [&](int kc, int s) {
        const int k0 = kc * 64;
        const unsigned stg = sbase + (unsigned)s * STG7;
        #pragma unroll
        for (int p = 0; p < 4; ++p) {
            int idx = tid + p*256;
            int row = idx >> 3, c = idx & 7;      // 128 rows x 8x16B
            cpa16(stg + (unsigned)(row*P2 + c*8)*2,
                  Af + (size_t)(t0+row)*DD + k0 + c*8);
            cpa16(stg + OFF_B7 + (unsigned)(row*P2 + c*8)*2,
                  Bf + (size_t)(n0+row)*DD + k0 + c*8);
        }
    };

    issue(0, 0);  CP_COMMIT();
    issue(1, 1);  CP_COMMIT();

    const int NC = DD/64;
    for (int kc = 0; kc < NC; ++kc) {
        if (kc + 1 < NC) { CP_WAIT(1); } else { CP_WAIT(0); }
        __syncthreads();
        if (kc + 2 < NC) {
            int sn = (kc + 2) % 3;
            issue(kc + 2, sn);
            CP_COMMIT();
        }

        const unsigned stg = sbase + (unsigned)(kc % 3) * STG7;
        #pragma unroll
        for (int k16 = 0; k16 < 4; ++k16) {
            unsigned af0[4], af1[4];
            ldsm4(af0, stg + aoff0 + k16*32);
            ldsm4(af1, stg + aoff1 + k16*32);
            #pragma unroll
            for (int jp = 0; jp < 4; ++jp) {
                unsigned bf[4];
                ldsm4(bf, stg + OFF_B7 + boff + (unsigned)(jp*16*P2)*2 + k16*32);
                MMA_F16(acc[0][2*jp],   af0, bf[0], bf[2]);
                MMA_F16(acc[0][2*jp+1], af0, bf[1], bf[3]);
                MMA_F16(acc[1][2*jp],   af1, bf[0], bf[2]);
                MMA_F16(acc[1][2*jp+1], af1, bf[1], bf[3]);
            }
        }
    }
    __syncthreads();   // protect smem reuse by epilogue-free kernels / next phase
}

// ---------------------------------------------------------------------------
// Kernel 1: QKV projections + bias + fused RoPE -> fp16 [b,h,s,hd].
// grid = (NT/128, DD/128, 3)
// ---------------------------------------------------------------------------
__global__ __launch_bounds__(256, 2) void qkv_gemm(
    const float* __restrict__ bq, const float* __restrict__ bk,
    const float* __restrict__ bv,
    const float* __restrict__ cosT, const float* __restrict__ sinT)
{
    extern __shared__ __align__(16) char dsm[];
    const unsigned sbase = smem_u32(dsm);

    const int z = blockIdx.z;
    const float* __restrict__ bp = (z==0) ? bq : (z==1) ? bk : bv;
    __half* __restrict__ df = (z==0) ? g_Qf : (z==1) ? g_Kf : g_Vf;

    const int t0 = blockIdx.x * 128;
    const int n0 = blockIdx.y * 128;
    const int lane = threadIdx.x & 31;
    const int warp = threadIdx.x >> 5;
    const int wm = warp & 3, wn = warp >> 2;

    float acc[2][8][4] = {};
    run_gemm8(g_xf, g_wf[z], t0, n0, sbase, acc);

    const int h = (n0 + wn*64) >> 6;     // warp's 64-col slice == one head
    float2 bia[8];
    #pragma unroll
    for (int j = 0; j < 8; ++j)
        bia[j] = *(const float2*)&bp[n0 + wn*64 + j*8 + (lane & 3)*2];

    #pragma unroll
    for (int am = 0; am < 2; ++am) {
        const int r0 = t0 + wm*32 + am*16 + (lane >> 2);
        #pragma unroll
        for (int half = 0; half < 2; ++half) {
            int t = r0 + half * 8;
            int b = t >> 11;
            int s = t & (SS - 1);
            size_t base = (((size_t)b*HH + h)*SS + s) * HDIM;
            if (z < 2) {
                #pragma unroll
                for (int j = 0; j < 4; ++j) {
                    int ch = j*8 + (lane & 3)*2;          // < 32
                    float v0a = acc[am][j  ][2*half]   + bia[j].x;
                    float v0b = acc[am][j  ][2*half+1] + bia[j].y;
                    float v1a = acc[am][j+4][2*half]   + bia[j+4].x;
                    float v1b = acc[am][j+4][2*half+1] + bia[j+4].y;
                    float2 c0 = *(const float2*)&cosT[s*HDIM + ch];
                    float2 s0 = *(const float2*)&sinT[s*HDIM + ch];
                    float2 c1 = *(const float2*)&cosT[s*HDIM + ch + 32];
                    float2 s1 = *(const float2*)&sinT[s*HDIM + ch + 32];
                    *(unsigned*)&df[base + ch]      = packh(v0a*c0.x - v1a*s0.x,
                                                            v0b*c0.y - v1b*s0.y);
                    *(unsigned*)&df[base + ch + 32] = packh(v1a*c1.x + v0a*s1.x,
                                                            v1b*c1.y + v0b*s1.y);
                }
            } else {
                #pragma unroll
                for (int j = 0; j < 8; ++j) {
                    int ch = j*8 + (lane & 3)*2;          // < 64
                    *(unsigned*)&df[base + ch] = packh(acc[am][j][2*half]   + bia[j].x,
                                                       acc[am][j][2*half+1] + bia[j].y);
                }
            }
        }
    }
}

// ---------------------------------------------------------------------------
// Kernel 3: output projection -> d_out [t, n] fp32. grid = (NT/128, DD/128)
// ---------------------------------------------------------------------------
__global__ __launch_bounds__(256, 2) void out_gemm(
    const float* __restrict__ bo, float* __restrict__ out)
{
    extern __shared__ __align__(16) char dsm[];
    const unsigned sbase = smem_u32(dsm);

    const int t0 = blockIdx.x * 128;
    const int n0 = blockIdx.y * 128;
    const int lane = threadIdx.x & 31;
    const int warp = threadIdx.x >> 5;
    const int wm = warp & 3, wn = warp >> 2;

    float acc[2][8][4] = {};
    run_gemm8(g_af, g_wf[3], t0, n0, sbase, acc);

    float2 bia[8];
    #pragma unroll
    for (int j = 0; j < 8; ++j)
        bia[j] = *(const float2*)&bo[n0 + wn*64 + j*8 + (lane & 3)*2];

    #pragma unroll
    for (int am = 0; am < 2; ++am) {
        const int r0 = t0 + wm*32 + am*16 + (lane >> 2);
        #pragma unroll
        for (int half = 0; half < 2; ++half) {
            int t = r0 + half * 8;
            #pragma unroll
            for (int j = 0; j < 8; ++j) {
                int n = n0 + wn*64 + j*8 + (lane & 3)*2;
                float2 o;
                o.x = acc[am][j][2*half]   + bia[j].x;
                o.y = acc[am][j][2*half+1] + bia[j].y;
                *(float2*)&out[(size_t)t*DD + n] = o;
            }
        }
    }
}

// ---------------------------------------------------------------------------
// Kernel 2: flash causal attention. 128q tile; cp.async double-buffered
// 128-key K/V superblocks with ONE barrier per superblock (issue after sync);
// Q fragments register-cached. grid = (16, 64).
// smem: Q[128][P2] + 2 stages x (K[128][P2] + V[128][P2]) = 92160 B
// ---------------------------------------------------------------------------
#define AQ_BYTES (128*P2*2)            // 18432
#define KV_STG   (2*128*P2*2)          // 36864 (K then V)
#define ASM_TOT  (AQ_BYTES + 2*KV_STG) // 92160

__global__ __launch_bounds__(256, 2) void attn_mma()
{
    extern __shared__ __align__(16) __half smh[];
    __half* Qf = smh;                         // [128][P2]

    const int tid  = threadIdx.x;
    const int lane = tid & 31;
    const int warp = tid >> 5;
    const int bh = blockIdx.y;
    const int qt = gridDim.x - 1 - blockIdx.x;   // long tiles first
    const int q0 = qt * 128;

    const size_t hb = (size_t)bh * SS * HDIM;
    const unsigned sbase = smem_u32(smh);

    // ---- load Q tile (sync LDG once)
    #pragma unroll
    for (int p = 0; p < 4; ++p) {
        int idx = tid + p*256;
        int row = idx >> 3, c8 = idx & 7;
        *(uint4*)&Qf[row*P2 + c8*8] = *(const uint4*)&g_Qf[hb + (size_t)(q0+row)*HDIM + c8*8];
    }

    const int g = lane >> 3, lr = lane & 7;
    const unsigned adQ = sbase + (unsigned)((warp*16 + (g&1)*8 + lr)*P2 + (g>>1)*8) * 2;
    const unsigned bKoff = (unsigned)(((g&1)*8 + lr)*P2 + (g>>1)*8) * 2;

    auto issue_kv = [&](int kb2, int s) {
        const int k0s = kb2 * 128;
        const unsigned stg = sbase + AQ_BYTES + (unsigned)s * KV_STG;
        #pragma unroll
        for (int p = 0; p < 4; ++p) {
            int idx = tid + p*256;
            int row = idx >> 3, c8 = idx & 7;
            size_t go = hb + (size_t)(k0s+row)*HDIM + c8*8;
            unsigned d = stg + (unsigned)(row*P2 + c8*8)*2;
            cpa16(d, g_Kf + go);
            cpa16(d + AQ_BYTES, g_Vf + go);
        }
    };

    issue_kv(0, 0);
    CP_COMMIT();

    float O[8][4] = {};
    float m0 = -1e30f, m1 = -1e30f, l0 = 0.f, l1 = 0.f;
    const float C = 0.18033688011112042f;   // (1/8) * log2(e)

    unsigned qreg[4][4];
    bool qloaded = false;

    for (int kb2 = 0; kb2 <= qt; ++kb2) {
        const int s = kb2 & 1;
        CP_WAIT(0);
        __syncthreads();
        if (kb2 < qt) {                 // safe: stage s^1 readers finished
            issue_kv(kb2 + 1, s ^ 1);   // before the sync above
            CP_COMMIT();
        }

        if (!qloaded) {       // Q fragments are loop-invariant: cache once
            #pragma unroll
            for (int k16 = 0; k16 < 4; ++k16)
                ldsm4(qreg[k16], adQ + k16*32);
            qloaded = true;
        }

        const unsigned stg = sbase + AQ_BYTES + (unsigned)s * KV_STG;
        const unsigned adK = stg + bKoff;
        const unsigned adV = stg + AQ_BYTES + bKoff;

        #pragma unroll
        for (int h2 = 0; h2 < 2; ++h2) {
            const int kb = 2*kb2 + h2;
            const int k0 = kb * 64;
            const unsigned kvo = (unsigned)(h2*64*P2) * 2;

            // ---- S = Q K^T (Q from registers)
            float z[8][4] = {};
            #pragma unroll
            for (int k16 = 0; k16 < 4; ++k16) {
                #pragma unroll
                for (int jp = 0; jp < 4; ++jp) {
                    unsigned kf[4];
                    ldsm4(kf, adK + kvo + (unsigned)(jp*16*P2)*2 + k16*32);
                    MMA_F16(z[2*jp],   qreg[k16], kf[0], kf[2]);
                    MMA_F16(z[2*jp+1], qreg[k16], kf[1], kf[3]);
                }
            }

            // ---- scale (log2 domain) + causal mask (boundary blocks only)
            const bool tail = (kb >= 2*qt);
            #pragma unroll
            for (int j = 0; j < 8; ++j) {
                #pragma unroll
                for (int c = 0; c < 4; ++c) {
                    int key = k0 + j*8 + (lane & 3)*2 + (c & 1);
                    int row = q0 + warp*16 + (lane >> 2) + (c >> 1)*8;
                    z[j][c] = (tail && key > row) ? -1e30f : z[j][c]*C;
                }
            }

            // ---- online softmax
            float ml0 = -1e30f, ml1 = -1e30f;
            #pragma unroll
            for (int j = 0; j < 8; ++j) {
                ml0 = fmaxf(ml0, fmaxf(z[j][0], z[j][1]));
                ml1 = fmaxf(ml1, fmaxf(z[j][2], z[j][3]));
            }
            ml0 = fmaxf(ml0, __shfl_xor_sync(0xffffffffu, ml0, 1));
            ml0 = fmaxf(ml0, __shfl_xor_sync(0xffffffffu, ml0, 2));
            ml1 = fmaxf(ml1, __shfl_xor_sync(0xffffffffu, ml1, 1));
            ml1 = fmaxf(ml1, __shfl_xor_sync(0xffffffffu, ml1, 2));
            float mn0 = fmaxf(m0, ml0), mn1 = fmaxf(m1, ml1);
            float al0 = exp2f(m0 - mn0), al1 = exp2f(m1 - mn1);
            m0 = mn0; m1 = mn1;

            float rs0 = 0.f, rs1 = 0.f;
            #pragma unroll
            for (int j = 0; j < 8; ++j) {
                z[j][0] = exp2f(z[j][0] - mn0);
                z[j][1] = exp2f(z[j][1] - mn0);
                z[j][2] = exp2f(z[j][2] - mn1);
                z[j][3] = exp2f(z[j][3] - mn1);
                rs0 += z[j][0] + z[j][1];
                rs1 += z[j][2] + z[j][3];
            }
            rs0 += __shfl_xor_sync(0xffffffffu, rs0, 1);
            rs0 += __shfl_xor_sync(0xffffffffu, rs0, 2);
            rs1 += __shfl_xor_sync(0xffffffffu, rs1, 1);
            rs1 += __shfl_xor_sync(0xffffffffu, rs1, 2);
            l0 = l0*al0 + rs0;
            l1 = l1*al1 + rs1;
            #pragma unroll
            for (int j = 0; j < 8; ++j) {
                O[j][0] *= al0; O[j][1] *= al0;
                O[j][2] *= al1; O[j][3] *= al1;
            }

            // ---- O += P V (P packed in registers)
            #pragma unroll
            for (int k16 = 0; k16 < 4; ++k16) {
                const int f0 = 2*k16, f1 = 2*k16 + 1;
                unsigned ah[4];
                ah[0] = packh(z[f0][0], z[f0][1]);
                ah[1] = packh(z[f0][2], z[f0][3]);
                ah[2] = packh(z[f1][0], z[f1][1]);
                ah[3] = packh(z[f1][2], z[f1][3]);
                #pragma unroll
                for (int jp = 0; jp < 4; ++jp) {
                    unsigned vf[4];
                    ldsm4t(vf, adV + kvo + (unsigned)(k16*16*P2 + jp*16)*2);
                    MMA_F16(O[2*jp],   ah, vf[0], vf[1]);
                    MMA_F16(O[2*jp+1], ah, vf[2], vf[3]);
                }
            }
        }
    }

    // ---- normalize + write att fp16 [t, d]
    const int b = bh >> 4;
    const int h = bh & 15;
    const float inv0 = 1.f / l0, inv1 = 1.f / l1;
    const int rlo = q0 + warp*16 + (lane >> 2);
    #pragma unroll
    for (int j = 0; j < 8; ++j) {
        int hd = h*HDIM + j*8 + (lane & 3)*2;
        *(unsigned*)&g_af[((size_t)(b*SS + rlo    ))*DD + hd] = packh(O[j][0]*inv0, O[j][1]*inv0);
        *(unsigned*)&g_af[((size_t)(b*SS + rlo + 8))*DD + hd] = packh(O[j][2]*inv1, O[j][3]*inv1);
    }
}

// ---------------------------------------------------------------------------
extern "C" void kernel_launch(void* const* d_in, const int* in_sizes, int n_in,
                              void* d_out, int out_size)
{
    const float* x    = (const float*)d_in[0];
    const float* cosT = (const float*)d_in[1];
    const float* sinT = (const float*)d_in[2];
    // d_in[3] = attn_mask (causal — applied analytically)
    const float* Wq = (const float*)d_in[4];
    const float* bq = (const float*)d_in[5];
    const float* Wk = (const float*)d_in[6];
    const float* bk = (const float*)d_in[7];
    const float* Wv = (const float*)d_in[8];
    const float* bv = (const float*)d_in[9];
    const float* Wo = (const float*)d_in[10];
    const float* bo = (const float*)d_in[11];
    float* out = (float*)d_out;

    // 0) fused fp32 -> fp16
    const size_t ntotal = (size_t)NT*DD + 4*(size_t)DD*DD;
    cvt_all<<<(int)(ntotal/1024), 256>>>(x, Wq, Wk, Wv, Wo);

    // 1) QKV + RoPE (3-stage pipeline)
    cudaFuncSetAttribute(qkv_gemm, cudaFuncAttributeMaxDynamicSharedMemorySize, GSM8);
    qkv_gemm<<<dim3(NT/128, DD/128, 3), 256, GSM8>>>(bq, bk, bv, cosT, sinT);

    // 2) causal flash attention (single-barrier superblocks)
    cudaFuncSetAttribute(attn_mma, cudaFuncAttributeMaxDynamicSharedMemorySize, ASM_TOT);
    attn_mma<<<dim3(SS/128, BB*HH), 256, ASM_TOT>>>();

    // 3) output projection (3-stage pipeline)
    cudaFuncSetAttribute(out_gemm, cudaFuncAttributeMaxDynamicSharedMemorySize, GSM8);
    out_gemm<<<dim3(NT/128, DD/128), 256, GSM8>>>(bo, out);
}